// round 15
// baseline (speedup 1.0000x reference)
#include <cuda_runtime.h>
#include <cuda_bf16.h>
#include <math.h>

#define NN 50000
#define EE 400000
#define ET 450000   // EE + NN self loops
#define EPSN 1e-5f
#define XPAD 66     // even -> aligned LDS.64 row pairs

// ---------------- scratch (device globals) -----------------------------------
__device__ float g_A[(size_t)NN * 128];       // h2
__device__ float g_B[(size_t)NN * 128];       // gat2 raw
__device__ float g_Z[(size_t)NN * 16];        // z[d][h][0..2] (float4 per (d,h)), normalized
__device__ float g_alS[(size_t)NN * 4];
__device__ float g_alD[(size_t)NN * 4];
__device__ float g_alS2[(size_t)NN * 2];
__device__ float g_alD2[(size_t)NN * 2];
__device__ float g_colstats[512];             // layer2 sums (self-cleaned in gath1z)
__device__ float g_zmom[36];                  // per head: S0,S1,S2,M00,M01,M02,M11,M12,M22
__device__ float g_eamsum[2];
__device__ float g_eamean[2];
__device__ float g_v1[8];
__device__ float g_v2[4];
__device__ float g_uS1[12], g_uD1[12];
__device__ float g_uS2[512], g_uD2[512];      // [k*2+h]
// CSR (pos-indexed arrays kept SEPARATE: independent chain heads for the gathers)
__device__ int g_cnt[NN];                     // counts (self-cleaned in gath1z)
__device__ int g_rowptr[NN + 1];              // post-fill: rowptr[d] == start of d+1
__device__ int g_csr_src[ET];
__device__ float2 g_csr_ea[ET];               // edge attrs in CSR order (self-loops = mean)

// f32x2 packed helpers
#define FMA2(acc, a, b) asm("fma.rn.f32x2 %0, %1, %2, %0;" : "+l"(acc) : "l"(a), "l"(b))
#define BCAST2(p, f)    asm("mov.b64 %0, {%1, %1};" : "=l"(p) : "f"(f))
#define UNPK2(lo, hi, p) asm("mov.b64 {%0, %1}, %2;" : "=f"(lo), "=f"(hi) : "l"(p))

// ---------------- merged: weight precomputes + degree count + ea mean --------
// blocks 0..3: uS2/uD2 (+ block 0: v1/v2/uS1/uD1). blocks >=4: edge loop.
__global__ void k_prepcm(const int* __restrict__ ei, const float* __restrict__ ea,
                         const float* __restrict__ We1, const float* __restrict__ ae1,
                         const float* __restrict__ We2, const float* __restrict__ ae2,
                         const float* __restrict__ W1, const float* __restrict__ as1,
                         const float* __restrict__ ad1,
                         const float* __restrict__ W2, const float* __restrict__ as2,
                         const float* __restrict__ ad2) {
    if (blockIdx.x >= 4) {
        // ---- cm part: dst-degree count + edge_attr sum ----
        int b = blockIdx.x - 4;
        int nb = gridDim.x - 4;
        float s0 = 0.f, s1 = 0.f;
        int st = nb * 256;
        for (int e = b * 256 + threadIdx.x; e < ET; e += st) {
            int d = (e < EE) ? ei[EE + e] : (e - EE);
            atomicAdd(&g_cnt[d], 1);
            if (e < EE) { s0 += ea[2 * e]; s1 += ea[2 * e + 1]; }
        }
        for (int o = 16; o; o >>= 1) {
            s0 += __shfl_down_sync(0xFFFFFFFFu, s0, o);
            s1 += __shfl_down_sync(0xFFFFFFFFu, s1, o);
        }
        __shared__ float sh[16];
        int lane = threadIdx.x & 31, wid = threadIdx.x >> 5;
        if (lane == 0) { sh[wid] = s0; sh[8 + wid] = s1; }
        __syncthreads();
        if (threadIdx.x == 0) {
            float a = 0.f, b2 = 0.f;
            for (int w = 0; w < 8; w++) { a += sh[w]; b2 += sh[8 + w]; }
            atomicAdd(&g_eamsum[0], a);
            atomicAdd(&g_eamsum[1], b2);
        }
        return;
    }
    // ---- prep part ----
    int gt = blockIdx.x * 256 + threadIdx.x;   // 0..1023
    {
        int which = gt >> 9;
        int kk = (gt & 511) >> 1, h = gt & 1;
        const float* a = which ? ad2 : as2;
        float s = 0.f;
        for (int d = 0; d < 64; d++) s += W2[kk * 128 + h * 64 + d] * a[h * 64 + d];
        if (which) g_uD2[kk * 2 + h] = s; else g_uS2[kk * 2 + h] = s;
    }
    if (blockIdx.x != 0) return;
    int t = threadIdx.x;
    if (t < 8) {
        int h = t >> 1, f = t & 1;
        float s = 0.f;
        for (int d = 0; d < 64; d++) s += We1[f * 256 + h * 64 + d] * ae1[h * 64 + d];
        g_v1[t] = s;
    } else if (t < 12) {
        int tt = t - 8, h = tt >> 1, f = tt & 1;
        float s = 0.f;
        for (int d = 0; d < 64; d++) s += We2[f * 128 + h * 64 + d] * ae2[h * 64 + d];
        g_v2[tt] = s;
    } else if (t < 24) {
        int idx = t - 12, f = idx >> 2, h = idx & 3;
        float s = 0.f;
        for (int d = 0; d < 64; d++) s += W1[f * 256 + h * 64 + d] * as1[h * 64 + d];
        g_uS1[idx] = s;
    } else if (t < 36) {
        int idx = t - 24, f = idx >> 2, h = idx & 3;
        float s = 0.f;
        for (int d = 0; d < 64; d++) s += W1[f * 256 + h * 64 + d] * ad1[h * 64 + d];
        g_uD1[idx] = s;
    }
}

// ---------------- single-kernel scan (+ layer1 node logits + eamean) ---------
__global__ void k_scan(const float* __restrict__ x) {
    __shared__ int sh[256];
    __shared__ int swr[8];
    int tid = threadIdx.x;
    int i = blockIdx.x * 256 + tid;

    if (blockIdx.x == 0 && tid == 0) {   // finalize edge-attr mean (for k_fill)
        g_eamean[0] = g_eamsum[0] / (float)EE;
        g_eamean[1] = g_eamsum[1] / (float)EE;
    }

    int limit = blockIdx.x << 8;
    int acc = 0;
    for (int t = tid; t < limit; t += 256) acc += g_cnt[t];
    for (int o = 16; o; o >>= 1) acc += __shfl_down_sync(0xFFFFFFFFu, acc, o);
    if ((tid & 31) == 0) swr[tid >> 5] = acc;

    int v = (i < NN) ? g_cnt[i] : 0;
    sh[tid] = v;
    __syncthreads();
    for (int o = 1; o < 256; o <<= 1) {
        int t = (tid >= o) ? sh[tid - o] : 0;
        __syncthreads();
        sh[tid] += t;
        __syncthreads();
    }
    int base = swr[0] + swr[1] + swr[2] + swr[3] + swr[4] + swr[5] + swr[6] + swr[7];
    if (i < NN) g_rowptr[i] = base + sh[tid] - v;   // exclusive start

    // independent: layer1 per-node attention logits
    if (i < NN) {
        float x0 = __ldg(&x[3 * i]), x1 = __ldg(&x[3 * i + 1]), x2 = __ldg(&x[3 * i + 2]);
        float4 s, d;
        s.x = x0 * g_uS1[0] + x1 * g_uS1[4] + x2 * g_uS1[8];
        s.y = x0 * g_uS1[1] + x1 * g_uS1[5] + x2 * g_uS1[9];
        s.z = x0 * g_uS1[2] + x1 * g_uS1[6] + x2 * g_uS1[10];
        s.w = x0 * g_uS1[3] + x1 * g_uS1[7] + x2 * g_uS1[11];
        d.x = x0 * g_uD1[0] + x1 * g_uD1[4] + x2 * g_uD1[8];
        d.y = x0 * g_uD1[1] + x1 * g_uD1[5] + x2 * g_uD1[9];
        d.z = x0 * g_uD1[2] + x1 * g_uD1[6] + x2 * g_uD1[10];
        d.w = x0 * g_uD1[3] + x1 * g_uD1[7] + x2 * g_uD1[11];
        *(float4*)&g_alS[i * 4] = s;
        *(float4*)&g_alD[i * 4] = d;
    }
}

// ---------------- fill: rowptr self-advance, 4 edges/thread ------------------
__global__ void k_fill(const int* __restrict__ ei, const float* __restrict__ ea) {
    int e0 = (blockIdx.x * blockDim.x + threadIdx.x) * 4;
#pragma unroll
    for (int u = 0; u < 4; u++) {
        int e = e0 + u;
        if (e >= ET) break;
        int s, d;
        float2 eav;
        if (e < EE) {
            s = ei[e]; d = ei[EE + e];
            eav = *(const float2*)&ea[2 * e];
        } else {
            s = e - EE; d = s;
            eav = make_float2(g_eamean[0], g_eamean[1]);
        }
        int pos = atomicAdd(&g_rowptr[d], 1);
        g_csr_src[pos] = s;
        g_csr_ea[pos] = eav;
    }
}
// After k_fill: g_rowptr[d] == start of node d+1. Range of d = [d?rowptr[d-1]:0, rowptr[d]).

// ---------------- layer1 gather: thread per (node, head) — 4x occupancy ------
// 4 consecutive lanes share a node: CSR/x loads broadcast within the sector.
__global__ void __launch_bounds__(256) k_gath1z(const float* __restrict__ x) {
    __shared__ float smom[8][36];
    int t = blockIdx.x * 256 + threadIdx.x;
    int n = t >> 2, h = t & 3;
    if (blockIdx.x == 0) {    // self-clean for later consumers
        g_colstats[threadIdx.x] = 0.f;
        g_colstats[256 + threadIdx.x] = 0.f;
    }
    bool valid = n < NN;
    if (valid && h == 0) g_cnt[n] = 0;   // ready for next replay's k_prepcm
    int p0 = 0, p1 = 0;
    if (valid) { p0 = n ? g_rowptr[n - 1] : 0; p1 = g_rowptr[n]; }
    float vh0 = g_v1[2 * h], vh1 = g_v1[2 * h + 1];
    float aD = valid ? g_alD[n * 4 + h] : 0.f;
    float z0 = 0.f, z1 = 0.f, z2 = 0.f, ws = 0.f;
#pragma unroll 2
    for (int pos = p0; pos < p1; pos++) {
        int s = __ldg(&g_csr_src[pos]);
        float2 e2 = __ldg(&g_csr_ea[pos]);
        float a = __ldg(&g_alS[s * 4 + h]) + aD + e2.x * vh0 + e2.y * vh1;
        a = a > 0.f ? a : 0.2f * a;
        float w = __expf(a);
        ws += w;
        z0 += w * __ldg(&x[3 * s]);
        z1 += w * __ldg(&x[3 * s + 1]);
        z2 += w * __ldg(&x[3 * s + 2]);
    }
    float r = valid ? 1.f / ws : 0.f;
    z0 *= r; z1 *= r; z2 *= r;
    if (valid) *(float4*)&g_Z[(size_t)(n * 4 + h) * 4] = make_float4(z0, z1, z2, 0.f);

    // per-head moments: shfl-reduce over lanes with same (lane&3)==h
    float p[9] = {z0, z1, z2, z0 * z0, z0 * z1, z0 * z2, z1 * z1, z1 * z2, z2 * z2};
#pragma unroll
    for (int i = 0; i < 9; i++) {
        float v = p[i];
        v += __shfl_xor_sync(0xFFFFFFFFu, v, 16);
        v += __shfl_xor_sync(0xFFFFFFFFu, v, 8);
        v += __shfl_xor_sync(0xFFFFFFFFu, v, 4);
        p[i] = v;
    }
    int lane = threadIdx.x & 31, wi = threadIdx.x >> 5;
    if (lane < 4) {
#pragma unroll
        for (int i = 0; i < 9; i++) smom[wi][lane * 9 + i] = p[i];
    }
    __syncthreads();
    // block reduce: 36 threads, one atomic each (low contention: 782 blocks)
    if (threadIdx.x < 36) {
        float s = 0.f;
#pragma unroll
        for (int w = 0; w < 8; w++) s += smom[w][threadIdx.x];
        atomicAdd(&g_zmom[threadIdx.x], s);
    }
}

// ---------------- fused GEMM2: inline layer1 norm, z-expand, f32x2 FMA -------
__global__ void __launch_bounds__(256) k_gemm2f(const float* __restrict__ W1,
                                                const float* __restrict__ W2,
                                                const float* __restrict__ b1,
                                                const float* __restrict__ ms1,
                                                const float* __restrict__ gw1,
                                                const float* __restrict__ gb1) {
    extern __shared__ float xs[];          // [256][XPAD] k-major
    __shared__ float cs[256], cf[256], us[512], ud[512], w1s[768], zs[64 * 16];
    __shared__ float zm[36];
    int tid = threadIdx.x;
    us[tid] = g_uS2[tid]; us[256 + tid] = g_uS2[256 + tid];
    ud[tid] = g_uD2[tid]; ud[256 + tid] = g_uD2[256 + tid];
    w1s[tid] = W1[tid]; w1s[256 + tid] = W1[256 + tid]; w1s[512 + tid] = W1[512 + tid];
    if (tid < 36) zm[tid] = g_zmom[tid];

    int r0 = blockIdx.x * 64;
    {   // stage z rows: 64 nodes x 4 float4
        int row = tid >> 2, part = tid & 3;
        float4 zv = make_float4(0.f, 0.f, 0.f, 0.f);
        if (r0 + row < NN) zv = *(const float4*)&g_Z[(size_t)((r0 + row) * 4 + part) * 4];
        *(float4*)&zs[(row * 4 + part) * 4] = zv;
    }
    __syncthreads();

    {   // inline layer-1 GraphNorm coefficients from z-moments
        int j = tid, h = j >> 6;
        float w0 = w1s[j], w1 = w1s[256 + j], w2 = w1s[512 + j];
        const float* m = zm + h * 9;
        float sum = w0 * m[0] + w1 * m[1] + w2 * m[2];
        float sq  = w0 * w0 * m[3] + w1 * w1 * m[6] + w2 * w2 * m[8]
                  + 2.f * (w0 * w1 * m[4] + w0 * w2 * m[5] + w1 * w2 * m[7]);
        float invN = 1.0f / NN;
        float bj = b1[j];
        float mean = sum * invN + bj;
        float cp = bj - mean * ms1[j];
        float var = sq * invN + 2.f * cp * (sum * invN) + cp * cp;
        float rstd = rsqrtf(var + EPSN);
        cs[j] = gw1[j] * rstd;
        cf[j] = cp * gw1[j] * rstd + gb1[j];
    }
    __syncthreads();

    // expand + norm + ELU into xs (k-major, transposed)
    for (int idx = tid; idx < 64 * 64; idx += 256) {
        int r = idx >> 6, kq = idx & 63;
        int k4 = kq * 4, h = kq >> 4;
        const float* zp = zs + (r * 4 + h) * 4;
        float z0 = zp[0], z1 = zp[1], z2 = zp[2];
#pragma unroll
        for (int cc = 0; cc < 4; cc++) {
            int c = k4 + cc;
            float v = z0 * w1s[c] + z1 * w1s[256 + c] + z2 * w1s[512 + c];
            float y = v * cs[c] + cf[c];
            y = y > 0.f ? y : expm1f(y);
            xs[c * XPAD + r] = y;
        }
    }
    __syncthreads();

    int tx = tid & 31, ty = tid >> 5;
    int c0 = tx * 4, rb = ty * 8;
    unsigned long long acc[4][4];
#pragma unroll
    for (int p = 0; p < 4; p++)
#pragma unroll
        for (int c = 0; c < 4; c++) acc[p][c] = 0ull;

    const float* W2p = W2 + c0;
#pragma unroll 4
    for (int k = 0; k < 256; k++) {
        const unsigned long long* xq = (const unsigned long long*)(xs + k * XPAD + rb);
        float4 w = __ldg((const float4*)(W2p + k * 128));
        unsigned long long xp0 = xq[0], xp1 = xq[1], xp2 = xq[2], xp3 = xq[3];
        unsigned long long wp;
        BCAST2(wp, w.x);
        FMA2(acc[0][0], xp0, wp); FMA2(acc[1][0], xp1, wp); FMA2(acc[2][0], xp2, wp); FMA2(acc[3][0], xp3, wp);
        BCAST2(wp, w.y);
        FMA2(acc[0][1], xp0, wp); FMA2(acc[1][1], xp1, wp); FMA2(acc[2][1], xp2, wp); FMA2(acc[3][1], xp3, wp);
        BCAST2(wp, w.z);
        FMA2(acc[0][2], xp0, wp); FMA2(acc[1][2], xp1, wp); FMA2(acc[2][2], xp2, wp); FMA2(acc[3][2], xp3, wp);
        BCAST2(wp, w.w);
        FMA2(acc[0][3], xp0, wp); FMA2(acc[1][3], xp1, wp); FMA2(acc[2][3], xp2, wp); FMA2(acc[3][3], xp3, wp);
    }

#pragma unroll
    for (int p = 0; p < 4; p++) {
        int row = r0 + rb + 2 * p;
        float l0, h0, l1, h1, l2, h2v, l3, h3;
        UNPK2(l0, h0, acc[p][0]);
        UNPK2(l1, h1, acc[p][1]);
        UNPK2(l2, h2v, acc[p][2]);
        UNPK2(l3, h3, acc[p][3]);
        if (row < NN)     *(float4*)(g_A + (size_t)row * 128 + c0)       = make_float4(l0, l1, l2, l3);
        if (row + 1 < NN) *(float4*)(g_A + (size_t)(row + 1) * 128 + c0) = make_float4(h0, h1, h2v, h3);
    }

    {   // layer-2 attention logits from the normalized tile
        int row = tid >> 2, q = tid & 3;
        int grow = r0 + row;
        const float* uu = (q < 2) ? (us + q) : (ud + (q - 2));
        float s = 0.f;
#pragma unroll 8
        for (int k = 0; k < 256; k++)
            s += xs[k * XPAD + row] * uu[k * 2];
        if (grow < NN) {
            if (q < 2) g_alS2[grow * 2 + q] = s;
            else       g_alD2[grow * 2 + (q - 2)] = s;
        }
    }
}

// ---------------- layer2 gather: warp per node, fused alpha, plain loop ------
__global__ void __launch_bounds__(256) k_gath2() {
    if (blockIdx.x == 0) {   // self-clean for next replay
        if (threadIdx.x < 36) g_zmom[threadIdx.x] = 0.f;
        if (threadIdx.x >= 36 && threadIdx.x < 38) g_eamsum[threadIdx.x - 36] = 0.f;
    }
    int d = (blockIdx.x * 256 + threadIdx.x) >> 5;
    if (d >= NN) return;
    int lane = threadIdx.x & 31;
    int j = lane * 4;
    int h = lane >> 4;
    int p0 = d ? g_rowptr[d - 1] : 0;
    int p1 = g_rowptr[d];
    float v20 = g_v2[2 * h], v21 = g_v2[2 * h + 1];
    float aD = g_alD2[d * 2 + h];
    float4 acc = make_float4(0.f, 0.f, 0.f, 0.f);
    float ws = 0.f;
#pragma unroll 2
    for (int pos = p0; pos < p1; pos++) {
        int s = __ldg(&g_csr_src[pos]);
        float2 e2 = __ldg(&g_csr_ea[pos]);
        float a = __ldg(&g_alS2[s * 2 + h]) + aD + e2.x * v20 + e2.y * v21;
        a = a > 0.f ? a : 0.2f * a;
        float w = __expf(a);
        float4 v = *(const float4*)(g_A + (size_t)s * 128 + j);
        ws += w;
        acc.x += v.x * w; acc.y += v.y * w; acc.z += v.z * w; acc.w += v.w * w;
    }
    float r = 1.f / ws;
    acc.x *= r; acc.y *= r; acc.z *= r; acc.w *= r;
    *(float4*)(g_B + (size_t)d * 128 + j) = acc;
}

// ---------------- layer2 GraphNorm column stats ------------------------------
__global__ void k_colsum2(const float* __restrict__ X, int rpb) {
    int j = threadIdx.x;   // 128
    int r0 = blockIdx.x * rpb, r1 = min(r0 + rpb, NN);
    float s = 0.f, q = 0.f;
    for (int r = r0; r < r1; r++) {
        float v = X[(size_t)r * 128 + j];
        s += v;
        q += v * v;
    }
    atomicAdd(&g_colstats[j], s);
    atomicAdd(&g_colstats[256 + j], q);
}

// ---------------- classifier (inline layer2 norm + ELU) ----------------------
__global__ void k_cls(const float* __restrict__ Wc, const float* __restrict__ bc,
                      const float* __restrict__ b2, const float* __restrict__ ms2,
                      const float* __restrict__ gw2, const float* __restrict__ gb2,
                      float* __restrict__ out) {
    __shared__ float wc[128 * 13];
    __shared__ float sbc[13];
    __shared__ float cs[128], cf[128];
    for (int i = threadIdx.x; i < 128 * 13; i += 256) wc[i] = Wc[i];
    if (threadIdx.x < 13) sbc[threadIdx.x] = bc[threadIdx.x];
    if (threadIdx.x < 128) {
        int j = threadIdx.x;
        float invN = 1.0f / NN;
        float sum = g_colstats[j], sq = g_colstats[256 + j];
        float bj = b2[j];
        float m = sum * invN + bj;
        float cp = bj - m * ms2[j];
        float var = sq * invN + 2.f * cp * (sum * invN) + cp * cp;
        float rstd = rsqrtf(var + EPSN);
        cs[j] = gw2[j] * rstd;
        cf[j] = cp * gw2[j] * rstd + gb2[j];
    }
    __syncthreads();
    int warp = (blockIdx.x * 256 + threadIdx.x) >> 5;
    int lane = threadIdx.x & 31;
    int nw = (gridDim.x * 256) >> 5;
    for (int n = warp; n < NN; n += nw) {
        float4 hv = *(const float4*)(g_B + (size_t)n * 128 + lane * 4);
        int kb = lane * 4;
        float y0 = hv.x * cs[kb + 0] + cf[kb + 0]; y0 = y0 > 0.f ? y0 : expm1f(y0);
        float y1 = hv.y * cs[kb + 1] + cf[kb + 1]; y1 = y1 > 0.f ? y1 : expm1f(y1);
        float y2 = hv.z * cs[kb + 2] + cf[kb + 2]; y2 = y2 > 0.f ? y2 : expm1f(y2);
        float y3 = hv.w * cs[kb + 3] + cf[kb + 3]; y3 = y3 > 0.f ? y3 : expm1f(y3);
#pragma unroll
        for (int c = 0; c < 13; c++) {
            float p = y0 * wc[kb * 13 + c] + y1 * wc[(kb + 1) * 13 + c]
                    + y2 * wc[(kb + 2) * 13 + c] + y3 * wc[(kb + 3) * 13 + c];
            for (int o = 16; o; o >>= 1) p += __shfl_down_sync(0xFFFFFFFFu, p, o);
            if (lane == 0) out[n * 13 + c] = p + sbc[c];
        }
    }
}

// ---------------- launch ------------------------------------------------------
extern "C" void kernel_launch(void* const* d_in, const int* in_sizes, int n_in,
                              void* d_out, int out_size) {
    const float* x    = (const float*)d_in[0];
    const int*   ei   = (const int*)d_in[1];
    const float* ea   = (const float*)d_in[2];
    const float* W1   = (const float*)d_in[3];
    const float* We1  = (const float*)d_in[4];
    const float* as1  = (const float*)d_in[5];
    const float* ad1  = (const float*)d_in[6];
    const float* ae1  = (const float*)d_in[7];
    const float* b1   = (const float*)d_in[8];
    const float* gn1w = (const float*)d_in[9];
    const float* gn1b = (const float*)d_in[10];
    const float* gn1m = (const float*)d_in[11];
    const float* W2   = (const float*)d_in[12];
    const float* We2  = (const float*)d_in[13];
    const float* as2  = (const float*)d_in[14];
    const float* ad2  = (const float*)d_in[15];
    const float* ae2  = (const float*)d_in[16];
    const float* b2   = (const float*)d_in[17];
    const float* gn2w = (const float*)d_in[18];
    const float* gn2b = (const float*)d_in[19];
    const float* gn2m = (const float*)d_in[20];
    const float* Wc   = (const float*)d_in[21];
    const float* bc   = (const float*)d_in[22];
    float* out = (float*)d_out;

    float* pB;
    cudaGetSymbolAddress((void**)&pB, g_B);

    cudaFuncSetAttribute(k_gemm2f, cudaFuncAttributeMaxDynamicSharedMemorySize, 256 * XPAD * 4);

    int nb = (NN + 255) / 256;   // 196

    k_prepcm<<<516, 256>>>(ei, ea, We1, ae1, We2, ae2, W1, as1, ad1, W2, as2, ad2); // 0
    k_scan<<<nb, 256>>>(x);                                            // 1
    k_fill<<<(ET / 4 + 255) / 256, 256>>>(ei, ea);                     // 2
    k_gath1z<<<(NN * 4 + 255) / 256, 256>>>(x);                        // 3  <- profiled
    k_gemm2f<<<(NN + 63) / 64, 256, 256 * XPAD * 4>>>(W1, W2, b1, gn1m, gn1w, gn1b); // 4
    k_gath2<<<(NN * 32 + 255) / 256, 256>>>();                         // 5
    k_colsum2<<<(NN + 127) / 128, 128>>>(pB, 128);                     // 6
    k_cls<<<512, 256>>>(Wc, bc, b2, gn2m, gn2w, gn2b, out);            // 7
}

// round 17
// speedup vs baseline: 1.2238x; 1.2238x over previous
#include <cuda_runtime.h>
#include <cuda_bf16.h>
#include <math.h>

#define NN 50000
#define EE 400000
#define ET 450000   // EE + NN self loops
#define EPSN 1e-5f
#define KC 64       // K chunk for tf32 GEMM
#define APAD 68     // xs row stride (64 k + 4)  -> A-frag LDS conflict-free
#define BPAD 136    // ws row stride (128 n + 8) -> B-frag LDS conflict-free

// ---------------- scratch (device globals) -----------------------------------
__device__ float g_A[(size_t)NN * 128];       // h2
__device__ float g_B[(size_t)NN * 128];       // gat2 raw
__device__ float g_Z[(size_t)NN * 16];        // z[d][h][0..2] (float4 per (d,h)), normalized
__device__ float g_alS[(size_t)NN * 4];
__device__ float g_alD[(size_t)NN * 4];
__device__ float g_alS2[(size_t)NN * 2];
__device__ float g_alD2[(size_t)NN * 2];
__device__ float g_colstats[512];             // layer2 sums (self-cleaned in gath1z)
__device__ float g_zmom[36];                  // per head: S0,S1,S2,M00,M01,M02,M11,M12,M22
__device__ float g_eamsum[2];
__device__ float g_eamean[2];
__device__ float g_v1[8];
__device__ float g_v2[4];
__device__ float g_uS1[12], g_uD1[12];
__device__ float g_uS2[512], g_uD2[512];      // [k*2+h]
// CSR (pos-indexed arrays kept SEPARATE: independent chain heads for the gathers)
__device__ int g_cnt[NN];                     // counts (self-cleaned in gath1z)
__device__ int g_rowptr[NN + 1];              // post-fill: rowptr[d] == start of d+1
__device__ int g_csr_src[ET];
__device__ float2 g_csr_ea[ET];               // edge attrs in CSR order (self-loops = mean)

// tf32 helpers
__device__ __forceinline__ float tf32r(float f) {
    unsigned u;
    asm("cvt.rna.tf32.f32 %0, %1;" : "=r"(u) : "f"(f));
    return __uint_as_float(u);
}
__device__ __forceinline__ void mma_tf32(float c[4], unsigned a0, unsigned a1,
                                         unsigned a2, unsigned a3,
                                         unsigned b0, unsigned b1) {
    asm volatile(
        "mma.sync.aligned.m16n8k8.row.col.f32.tf32.tf32.f32 "
        "{%0,%1,%2,%3},{%4,%5,%6,%7},{%8,%9},{%0,%1,%2,%3};"
        : "+f"(c[0]), "+f"(c[1]), "+f"(c[2]), "+f"(c[3])
        : "r"(a0), "r"(a1), "r"(a2), "r"(a3), "r"(b0), "r"(b1));
}

// ---------------- merged: weight precomputes + degree count + ea mean --------
__global__ void k_prepcm(const int* __restrict__ ei, const float* __restrict__ ea,
                         const float* __restrict__ We1, const float* __restrict__ ae1,
                         const float* __restrict__ We2, const float* __restrict__ ae2,
                         const float* __restrict__ W1, const float* __restrict__ as1,
                         const float* __restrict__ ad1,
                         const float* __restrict__ W2, const float* __restrict__ as2,
                         const float* __restrict__ ad2) {
    if (blockIdx.x >= 4) {
        int b = blockIdx.x - 4;
        int nb = gridDim.x - 4;
        float s0 = 0.f, s1 = 0.f;
        int st = nb * 256;
        for (int e = b * 256 + threadIdx.x; e < ET; e += st) {
            int d = (e < EE) ? ei[EE + e] : (e - EE);
            atomicAdd(&g_cnt[d], 1);
            if (e < EE) { s0 += ea[2 * e]; s1 += ea[2 * e + 1]; }
        }
        for (int o = 16; o; o >>= 1) {
            s0 += __shfl_down_sync(0xFFFFFFFFu, s0, o);
            s1 += __shfl_down_sync(0xFFFFFFFFu, s1, o);
        }
        __shared__ float sh[16];
        int lane = threadIdx.x & 31, wid = threadIdx.x >> 5;
        if (lane == 0) { sh[wid] = s0; sh[8 + wid] = s1; }
        __syncthreads();
        if (threadIdx.x == 0) {
            float a = 0.f, b2 = 0.f;
            for (int w = 0; w < 8; w++) { a += sh[w]; b2 += sh[8 + w]; }
            atomicAdd(&g_eamsum[0], a);
            atomicAdd(&g_eamsum[1], b2);
        }
        return;
    }
    int gt = blockIdx.x * 256 + threadIdx.x;   // 0..1023
    {
        int which = gt >> 9;
        int kk = (gt & 511) >> 1, h = gt & 1;
        const float* a = which ? ad2 : as2;
        float s = 0.f;
        for (int d = 0; d < 64; d++) s += W2[kk * 128 + h * 64 + d] * a[h * 64 + d];
        if (which) g_uD2[kk * 2 + h] = s; else g_uS2[kk * 2 + h] = s;
    }
    if (blockIdx.x != 0) return;
    int t = threadIdx.x;
    if (t < 8) {
        int h = t >> 1, f = t & 1;
        float s = 0.f;
        for (int d = 0; d < 64; d++) s += We1[f * 256 + h * 64 + d] * ae1[h * 64 + d];
        g_v1[t] = s;
    } else if (t < 12) {
        int tt = t - 8, h = tt >> 1, f = tt & 1;
        float s = 0.f;
        for (int d = 0; d < 64; d++) s += We2[f * 128 + h * 64 + d] * ae2[h * 64 + d];
        g_v2[tt] = s;
    } else if (t < 24) {
        int idx = t - 12, f = idx >> 2, h = idx & 3;
        float s = 0.f;
        for (int d = 0; d < 64; d++) s += W1[f * 256 + h * 64 + d] * as1[h * 64 + d];
        g_uS1[idx] = s;
    } else if (t < 36) {
        int idx = t - 24, f = idx >> 2, h = idx & 3;
        float s = 0.f;
        for (int d = 0; d < 64; d++) s += W1[f * 256 + h * 64 + d] * ad1[h * 64 + d];
        g_uD1[idx] = s;
    }
}

// ---------------- single-kernel scan (+ layer1 node logits + eamean) ---------
__global__ void k_scan(const float* __restrict__ x) {
    __shared__ int sh[256];
    __shared__ int swr[8];
    int tid = threadIdx.x;
    int i = blockIdx.x * 256 + tid;

    if (blockIdx.x == 0 && tid == 0) {
        g_eamean[0] = g_eamsum[0] / (float)EE;
        g_eamean[1] = g_eamsum[1] / (float)EE;
    }

    int limit = blockIdx.x << 8;
    int acc = 0;
    for (int t = tid; t < limit; t += 256) acc += g_cnt[t];
    for (int o = 16; o; o >>= 1) acc += __shfl_down_sync(0xFFFFFFFFu, acc, o);
    if ((tid & 31) == 0) swr[tid >> 5] = acc;

    int v = (i < NN) ? g_cnt[i] : 0;
    sh[tid] = v;
    __syncthreads();
    for (int o = 1; o < 256; o <<= 1) {
        int t = (tid >= o) ? sh[tid - o] : 0;
        __syncthreads();
        sh[tid] += t;
        __syncthreads();
    }
    int base = swr[0] + swr[1] + swr[2] + swr[3] + swr[4] + swr[5] + swr[6] + swr[7];
    if (i < NN) g_rowptr[i] = base + sh[tid] - v;   // exclusive start

    if (i < NN) {
        float x0 = __ldg(&x[3 * i]), x1 = __ldg(&x[3 * i + 1]), x2 = __ldg(&x[3 * i + 2]);
        float4 s, d;
        s.x = x0 * g_uS1[0] + x1 * g_uS1[4] + x2 * g_uS1[8];
        s.y = x0 * g_uS1[1] + x1 * g_uS1[5] + x2 * g_uS1[9];
        s.z = x0 * g_uS1[2] + x1 * g_uS1[6] + x2 * g_uS1[10];
        s.w = x0 * g_uS1[3] + x1 * g_uS1[7] + x2 * g_uS1[11];
        d.x = x0 * g_uD1[0] + x1 * g_uD1[4] + x2 * g_uD1[8];
        d.y = x0 * g_uD1[1] + x1 * g_uD1[5] + x2 * g_uD1[9];
        d.z = x0 * g_uD1[2] + x1 * g_uD1[6] + x2 * g_uD1[10];
        d.w = x0 * g_uD1[3] + x1 * g_uD1[7] + x2 * g_uD1[11];
        *(float4*)&g_alS[i * 4] = s;
        *(float4*)&g_alD[i * 4] = d;
    }
}

// ---------------- fill: rowptr self-advance, 4 edges/thread ------------------
__global__ void k_fill(const int* __restrict__ ei, const float* __restrict__ ea) {
    int e0 = (blockIdx.x * blockDim.x + threadIdx.x) * 4;
#pragma unroll
    for (int u = 0; u < 4; u++) {
        int e = e0 + u;
        if (e >= ET) break;
        int s, d;
        float2 eav;
        if (e < EE) {
            s = ei[e]; d = ei[EE + e];
            eav = *(const float2*)&ea[2 * e];
        } else {
            s = e - EE; d = s;
            eav = make_float2(g_eamean[0], g_eamean[1]);
        }
        int pos = atomicAdd(&g_rowptr[d], 1);
        g_csr_src[pos] = s;
        g_csr_ea[pos] = eav;
    }
}

// ---------------- layer1 gather: thread per (node, head) ---------------------
__global__ void __launch_bounds__(256) k_gath1z(const float* __restrict__ x) {
    __shared__ float smom[8][36];
    int t = blockIdx.x * 256 + threadIdx.x;
    int n = t >> 2, h = t & 3;
    if (blockIdx.x == 0) {
        g_colstats[threadIdx.x] = 0.f;
        g_colstats[256 + threadIdx.x] = 0.f;
    }
    bool valid = n < NN;
    if (valid && h == 0) g_cnt[n] = 0;
    int p0 = 0, p1 = 0;
    if (valid) { p0 = n ? g_rowptr[n - 1] : 0; p1 = g_rowptr[n]; }
    float vh0 = g_v1[2 * h], vh1 = g_v1[2 * h + 1];
    float aD = valid ? g_alD[n * 4 + h] : 0.f;
    float z0 = 0.f, z1 = 0.f, z2 = 0.f, ws = 0.f;
#pragma unroll 2
    for (int pos = p0; pos < p1; pos++) {
        int s = __ldg(&g_csr_src[pos]);
        float2 e2 = __ldg(&g_csr_ea[pos]);
        float a = __ldg(&g_alS[s * 4 + h]) + aD + e2.x * vh0 + e2.y * vh1;
        a = a > 0.f ? a : 0.2f * a;
        float w = __expf(a);
        ws += w;
        z0 += w * __ldg(&x[3 * s]);
        z1 += w * __ldg(&x[3 * s + 1]);
        z2 += w * __ldg(&x[3 * s + 2]);
    }
    float r = valid ? 1.f / ws : 0.f;
    z0 *= r; z1 *= r; z2 *= r;
    if (valid) *(float4*)&g_Z[(size_t)(n * 4 + h) * 4] = make_float4(z0, z1, z2, 0.f);

    float p[9] = {z0, z1, z2, z0 * z0, z0 * z1, z0 * z2, z1 * z1, z1 * z2, z2 * z2};
#pragma unroll
    for (int i = 0; i < 9; i++) {
        float v = p[i];
        v += __shfl_xor_sync(0xFFFFFFFFu, v, 16);
        v += __shfl_xor_sync(0xFFFFFFFFu, v, 8);
        v += __shfl_xor_sync(0xFFFFFFFFu, v, 4);
        p[i] = v;
    }
    int lane = threadIdx.x & 31, wi = threadIdx.x >> 5;
    if (lane < 4) {
#pragma unroll
        for (int i = 0; i < 9; i++) smom[wi][lane * 9 + i] = p[i];
    }
    __syncthreads();
    if (threadIdx.x < 36) {
        float s = 0.f;
#pragma unroll
        for (int w = 0; w < 8; w++) s += smom[w][threadIdx.x];
        atomicAdd(&g_zmom[threadIdx.x], s);
    }
}

// ---------------- tf32 tensor-core GEMM2: norm+ELU expand, mma, logits -------
// h2[N,128] = elu(norm(z @ W1)) @ W2 via mma.sync m16n8k8 tf32, K chunked by 64.
__global__ void __launch_bounds__(256) k_gemm2t(const float* __restrict__ W1,
                                                const float* __restrict__ W2,
                                                const float* __restrict__ b1,
                                                const float* __restrict__ ms1,
                                                const float* __restrict__ gw1,
                                                const float* __restrict__ gb1) {
    extern __shared__ float dyn[];
    float* xs = dyn;                  // [64][APAD] row-major features (tf32-rounded)
    float* wsm = dyn + 64 * APAD;     // [KC][BPAD] W2 chunk (tf32-rounded)
    __shared__ float cs[256], cf[256], us[512], ud[512], w1s[768], zs[64 * 16];
    __shared__ float zm[36];
    int tid = threadIdx.x;
    us[tid] = g_uS2[tid]; us[256 + tid] = g_uS2[256 + tid];
    ud[tid] = g_uD2[tid]; ud[256 + tid] = g_uD2[256 + tid];
    w1s[tid] = W1[tid]; w1s[256 + tid] = W1[256 + tid]; w1s[512 + tid] = W1[512 + tid];
    if (tid < 36) zm[tid] = g_zmom[tid];

    int r0 = blockIdx.x * 64;
    {   // stage z rows: 64 nodes x 4 float4
        int row = tid >> 2, part = tid & 3;
        float4 zv = make_float4(0.f, 0.f, 0.f, 0.f);
        if (r0 + row < NN) zv = *(const float4*)&g_Z[(size_t)((r0 + row) * 4 + part) * 4];
        *(float4*)&zs[(row * 4 + part) * 4] = zv;
    }
    __syncthreads();

    {   // inline layer-1 GraphNorm coefficients from z-moments
        int j = tid, h = j >> 6;
        float w0 = w1s[j], w1 = w1s[256 + j], w2 = w1s[512 + j];
        const float* m = zm + h * 9;
        float sum = w0 * m[0] + w1 * m[1] + w2 * m[2];
        float sq  = w0 * w0 * m[3] + w1 * w1 * m[6] + w2 * w2 * m[8]
                  + 2.f * (w0 * w1 * m[4] + w0 * w2 * m[5] + w1 * w2 * m[7]);
        float invN = 1.0f / NN;
        float bj = b1[j];
        float mean = sum * invN + bj;
        float cp = bj - mean * ms1[j];
        float var = sq * invN + 2.f * cp * (sum * invN) + cp * cp;
        float rstd = rsqrtf(var + EPSN);
        cs[j] = gw1[j] * rstd;
        cf[j] = cp * gw1[j] * rstd + gb1[j];
    }

    int warp = tid >> 5, lane = tid & 31;
    int gid = lane >> 2, tg = lane & 3;
    int rt = warp & 3;            // row tile: rows rt*16 .. +15
    int chalf = warp >> 2;        // col half: cols chalf*64 .. +63
    float acc[8][4];
#pragma unroll
    for (int nt = 0; nt < 8; nt++)
#pragma unroll
        for (int q = 0; q < 4; q++) acc[nt][q] = 0.f;

    int lrow = tid >> 2, lq = tid & 3;        // logits: (row, quadrant)
    const float* uu = (lq < 2) ? (us + lq) : (ud + (lq - 2));
    float logit = 0.f;

    for (int kc = 0; kc < 4; kc++) {
        int kb0 = kc * KC;
        __syncthreads();   // protect xs/wsm reuse from previous chunk's readers
        // stage W2 chunk (tf32-rounded)
        for (int idx = tid; idx < KC * 32; idx += 256) {
            int k = idx >> 5;
            int n4 = (idx & 31) * 4;
            float4 w = __ldg((const float4*)(W2 + (size_t)(kb0 + k) * 128 + n4));
            wsm[k * BPAD + n4 + 0] = tf32r(w.x);
            wsm[k * BPAD + n4 + 1] = tf32r(w.y);
            wsm[k * BPAD + n4 + 2] = tf32r(w.z);
            wsm[k * BPAD + n4 + 3] = tf32r(w.w);
        }
        // expand + norm + ELU chunk into xs (row-major, tf32-rounded)
        for (int idx = tid; idx < 64 * 16; idx += 256) {
            int rr = idx >> 4, kq = idx & 15;
            int kl4 = kq * 4;
            int c4 = kb0 + kl4;
            int h = c4 >> 6;
            const float* zp = zs + (rr * 4 + h) * 4;
            float z0 = zp[0], z1 = zp[1], z2 = zp[2];
#pragma unroll
            for (int cc = 0; cc < 4; cc++) {
                int c = c4 + cc;
                float v = z0 * w1s[c] + z1 * w1s[256 + c] + z2 * w1s[512 + c];
                float y = v * cs[c] + cf[c];
                y = y > 0.f ? y : expm1f(y);
                xs[rr * APAD + kl4 + cc] = tf32r(y);
            }
        }
        __syncthreads();

        // mma: 8 k-steps of 8
        const float* xb = xs + rt * 16 * APAD;
#pragma unroll
        for (int ks = 0; ks < 8; ks++) {
            int kb = ks * 8;
            unsigned a0 = __float_as_uint(xb[gid * APAD + kb + tg]);
            unsigned a1 = __float_as_uint(xb[(gid + 8) * APAD + kb + tg]);
            unsigned a2 = __float_as_uint(xb[gid * APAD + kb + tg + 4]);
            unsigned a3 = __float_as_uint(xb[(gid + 8) * APAD + kb + tg + 4]);
#pragma unroll
            for (int nt = 0; nt < 8; nt++) {
                int nb = chalf * 64 + nt * 8;
                unsigned b0 = __float_as_uint(wsm[(kb + tg) * BPAD + nb + gid]);
                unsigned b1 = __float_as_uint(wsm[(kb + tg + 4) * BPAD + nb + gid]);
                mma_tf32(acc[nt], a0, a1, a2, a3, b0, b1);
            }
        }

        // logits partial from this chunk
        {
            float s = 0.f;
#pragma unroll 8
            for (int k = 0; k < KC; k++)
                s += xs[lrow * APAD + k] * uu[(kb0 + k) * 2];
            logit += s;
        }
    }

    // write h2 tile
#pragma unroll
    for (int nt = 0; nt < 8; nt++) {
        int col = chalf * 64 + nt * 8 + 2 * tg;
        int row = r0 + rt * 16 + gid;
        if (row < NN)     *(float2*)(g_A + (size_t)row * 128 + col)       = make_float2(acc[nt][0], acc[nt][1]);
        if (row + 8 < NN) *(float2*)(g_A + (size_t)(row + 8) * 128 + col) = make_float2(acc[nt][2], acc[nt][3]);
    }

    // write layer-2 logits
    int grow = r0 + lrow;
    if (grow < NN) {
        if (lq < 2) g_alS2[grow * 2 + lq] = logit;
        else        g_alD2[grow * 2 + (lq - 2)] = logit;
    }
}

// ---------------- layer2 gather: warp per node, fused alpha ------------------
__global__ void __launch_bounds__(256) k_gath2() {
    if (blockIdx.x == 0) {
        if (threadIdx.x < 36) g_zmom[threadIdx.x] = 0.f;
        if (threadIdx.x >= 36 && threadIdx.x < 38) g_eamsum[threadIdx.x - 36] = 0.f;
    }
    int d = (blockIdx.x * 256 + threadIdx.x) >> 5;
    if (d >= NN) return;
    int lane = threadIdx.x & 31;
    int j = lane * 4;
    int h = lane >> 4;
    int p0 = d ? g_rowptr[d - 1] : 0;
    int p1 = g_rowptr[d];
    float v20 = g_v2[2 * h], v21 = g_v2[2 * h + 1];
    float aD = g_alD2[d * 2 + h];
    float4 acc = make_float4(0.f, 0.f, 0.f, 0.f);
    float ws = 0.f;
#pragma unroll 2
    for (int pos = p0; pos < p1; pos++) {
        int s = __ldg(&g_csr_src[pos]);
        float2 e2 = __ldg(&g_csr_ea[pos]);
        float a = __ldg(&g_alS2[s * 2 + h]) + aD + e2.x * v20 + e2.y * v21;
        a = a > 0.f ? a : 0.2f * a;
        float w = __expf(a);
        float4 v = *(const float4*)(g_A + (size_t)s * 128 + j);
        ws += w;
        acc.x += v.x * w; acc.y += v.y * w; acc.z += v.z * w; acc.w += v.w * w;
    }
    float r = 1.f / ws;
    acc.x *= r; acc.y *= r; acc.z *= r; acc.w *= r;
    *(float4*)(g_B + (size_t)d * 128 + j) = acc;
}

// ---------------- layer2 GraphNorm column stats ------------------------------
__global__ void k_colsum2(const float* __restrict__ X, int rpb) {
    int j = threadIdx.x;   // 128
    int r0 = blockIdx.x * rpb, r1 = min(r0 + rpb, NN);
    float s = 0.f, q = 0.f;
    for (int r = r0; r < r1; r++) {
        float v = X[(size_t)r * 128 + j];
        s += v;
        q += v * v;
    }
    atomicAdd(&g_colstats[j], s);
    atomicAdd(&g_colstats[256 + j], q);
}

// ---------------- classifier (inline layer2 norm + ELU) ----------------------
__global__ void k_cls(const float* __restrict__ Wc, const float* __restrict__ bc,
                      const float* __restrict__ b2, const float* __restrict__ ms2,
                      const float* __restrict__ gw2, const float* __restrict__ gb2,
                      float* __restrict__ out) {
    __shared__ float wc[128 * 13];
    __shared__ float sbc[13];
    __shared__ float cs[128], cf[128];
    for (int i = threadIdx.x; i < 128 * 13; i += 256) wc[i] = Wc[i];
    if (threadIdx.x < 13) sbc[threadIdx.x] = bc[threadIdx.x];
    if (threadIdx.x < 128) {
        int j = threadIdx.x;
        float invN = 1.0f / NN;
        float sum = g_colstats[j], sq = g_colstats[256 + j];
        float bj = b2[j];
        float m = sum * invN + bj;
        float cp = bj - m * ms2[j];
        float var = sq * invN + 2.f * cp * (sum * invN) + cp * cp;
        float rstd = rsqrtf(var + EPSN);
        cs[j] = gw2[j] * rstd;
        cf[j] = cp * gw2[j] * rstd + gb2[j];
    }
    __syncthreads();
    int warp = (blockIdx.x * 256 + threadIdx.x) >> 5;
    int lane = threadIdx.x & 31;
    int nw = (gridDim.x * 256) >> 5;
    for (int n = warp; n < NN; n += nw) {
        float4 hv = *(const float4*)(g_B + (size_t)n * 128 + lane * 4);
        int kb = lane * 4;
        float y0 = hv.x * cs[kb + 0] + cf[kb + 0]; y0 = y0 > 0.f ? y0 : expm1f(y0);
        float y1 = hv.y * cs[kb + 1] + cf[kb + 1]; y1 = y1 > 0.f ? y1 : expm1f(y1);
        float y2 = hv.z * cs[kb + 2] + cf[kb + 2]; y2 = y2 > 0.f ? y2 : expm1f(y2);
        float y3 = hv.w * cs[kb + 3] + cf[kb + 3]; y3 = y3 > 0.f ? y3 : expm1f(y3);
#pragma unroll
        for (int c = 0; c < 13; c++) {
            float p = y0 * wc[kb * 13 + c] + y1 * wc[(kb + 1) * 13 + c]
                    + y2 * wc[(kb + 2) * 13 + c] + y3 * wc[(kb + 3) * 13 + c];
            for (int o = 16; o; o >>= 1) p += __shfl_down_sync(0xFFFFFFFFu, p, o);
            if (lane == 0) out[n * 13 + c] = p + sbc[c];
        }
    }
}

// ---------------- launch ------------------------------------------------------
extern "C" void kernel_launch(void* const* d_in, const int* in_sizes, int n_in,
                              void* d_out, int out_size) {
    const float* x    = (const float*)d_in[0];
    const int*   ei   = (const int*)d_in[1];
    const float* ea   = (const float*)d_in[2];
    const float* W1   = (const float*)d_in[3];
    const float* We1  = (const float*)d_in[4];
    const float* as1  = (const float*)d_in[5];
    const float* ad1  = (const float*)d_in[6];
    const float* ae1  = (const float*)d_in[7];
    const float* b1   = (const float*)d_in[8];
    const float* gn1w = (const float*)d_in[9];
    const float* gn1b = (const float*)d_in[10];
    const float* gn1m = (const float*)d_in[11];
    const float* W2   = (const float*)d_in[12];
    const float* We2  = (const float*)d_in[13];
    const float* as2  = (const float*)d_in[14];
    const float* ad2  = (const float*)d_in[15];
    const float* ae2  = (const float*)d_in[16];
    const float* b2   = (const float*)d_in[17];
    const float* gn2w = (const float*)d_in[18];
    const float* gn2b = (const float*)d_in[19];
    const float* gn2m = (const float*)d_in[20];
    const float* Wc   = (const float*)d_in[21];
    const float* bc   = (const float*)d_in[22];
    float* out = (float*)d_out;

    float* pB;
    cudaGetSymbolAddress((void**)&pB, g_B);

    int dynsm = (64 * APAD + KC * BPAD) * 4;   // 52224 B
    cudaFuncSetAttribute(k_gemm2t, cudaFuncAttributeMaxDynamicSharedMemorySize, dynsm);

    int nb = (NN + 255) / 256;   // 196

    k_prepcm<<<516, 256>>>(ei, ea, We1, ae1, We2, ae2, W1, as1, ad1, W2, as2, ad2); // 0
    k_scan<<<nb, 256>>>(x);                                            // 1
    k_fill<<<(ET / 4 + 255) / 256, 256>>>(ei, ea);                     // 2
    k_gath1z<<<(NN * 4 + 255) / 256, 256>>>(x);                        // 3  <- profiled
    k_gemm2t<<<(NN + 63) / 64, 256, dynsm>>>(W1, W2, b1, gn1m, gn1w, gn1b); // 4
    k_gath2<<<(NN * 32 + 255) / 256, 256>>>();                         // 5
    k_colsum2<<<(NN + 127) / 128, 128>>>(pB, 128);                     // 6
    k_cls<<<512, 256>>>(Wc, bc, b2, gn2m, gn2w, gn2b, out);            // 7
}